// round 15
// baseline (speedup 1.0000x reference)
#include <cuda_runtime.h>
#include <cuda_fp16.h>
#include <math.h>

#define NMAX 50000
#define EMAX 800000
#define NBLK 148
#define NTHR 1024
#define BW   256                      // build warps (0-7) thread count
#define NT_B (NBLK * BW)
#define NT_A (NBLK * NTHR)
#define NGRP 3                        // gemm groups (256 thr each, warps 8-31)
#define WS_BYTES (NGRP * 32 * 128 * 4)        // 49152
#define XS_BYTES (NGRP * 32 * 68 * 4)         // 26112
#define SMEM_BYTES (WS_BYTES + XS_BYTES)      // 75264

typedef unsigned long long ull;

// ---------------- scratch ----------------
__device__ float  g_dinv[NMAX];
__device__ int    g_deg[NMAX];            // zeroed at end of this kernel for next replay
__device__ int    g_off[NMAX + 1];
__device__ int    g_cur[NMAX];
__device__ int    g_bsum[NBLK + 8];
__device__ int    g_csr[EMAX];            // src only
__device__ __half g_h1[(size_t)NMAX * 128];
__device__ float  g_h2[(size_t)NMAX * 16];   // (relu(agg1+b1) @ W2) * dinv

// ---------------- barriers ----------------
__device__ unsigned g_cnt[2] = {0, 0};
__device__ volatile unsigned g_gen[2] = {0, 0};

__device__ __forceinline__ void gspin(int slot, unsigned nb) {
    __threadfence();
    unsigned g = g_gen[slot];
    if (atomicAdd(&g_cnt[slot], 1u) == nb - 1u) {
        g_cnt[slot] = 0u;
        __threadfence();
        g_gen[slot] = g + 1u;
    } else {
        while (g_gen[slot] == g) __nanosleep(64);
    }
}
__device__ __forceinline__ void bar_named(int id, int cnt) {
    asm volatile("bar.sync %0, %1;" :: "r"(id), "r"(cnt) : "memory");
}
__device__ __forceinline__ void gbar_full() {       // all 1024 thr, all blocks
    __syncthreads();
    if (threadIdx.x == 0) gspin(1, NBLK);
    __syncthreads();
}
__device__ __forceinline__ void gbar_build() {      // warps 0-7 only, all blocks
    bar_named(4, BW);
    if (threadIdx.x == 0) gspin(0, NBLK);
    bar_named(4, BW);
}

// ---------------- f32x2 helpers ----------------
__device__ __forceinline__ ull pk2(float a, float b) {
    ull r; asm("mov.b64 %0, {%1, %2};" : "=l"(r) : "f"(a), "f"(b)); return r;
}
__device__ __forceinline__ float2 up2(ull v) {
    float2 r; asm("mov.b64 {%0, %1}, %2;" : "=f"(r.x), "=f"(r.y) : "l"(v)); return r;
}
__device__ __forceinline__ ull ffma2(ull a, ull b, ull c) {
    ull d; asm("fma.rn.f32x2 %0, %1, %2, %3;" : "=l"(d) : "l"(a), "l"(b), "l"(c)); return d;
}
__device__ __forceinline__ void fma8p(ull* acc, uint4 u, float w) {
    ull ww = pk2(w, w);
    __half2* h = (__half2*)&u;
#pragma unroll
    for (int j = 0; j < 4; ++j) {
        float2 f = __half22float2(h[j]);
        acc[j] = ffma2(pk2(f.x, f.y), ww, acc[j]);
    }
}

// ==================== the whole GCN in one persistent kernel ====================
extern "C" __global__ void __launch_bounds__(NTHR, 1)
k_all(const float* __restrict__ x, const int* __restrict__ ei,
      const float* __restrict__ W1, const float* __restrict__ b1,
      const float* __restrict__ W2, const float* __restrict__ b2,
      float* __restrict__ out, int n, int E) {
    extern __shared__ char smem_dyn[];
    __shared__ int wsum[8];
    __shared__ int s_carry;
    int tid = threadIdx.x, lane = tid & 31;
    int b = blockIdx.x;

    // ================= PHASE 1: build (warps 0-7)  ||  GEMM1 (warps 8-31) =================
    if (tid < BW) {
        // ---------- CSR build on 256 threads ----------
        int wid = tid >> 5;                       // 0..7
        int gt = b * BW + tid;
        // dtype detect, per-warp (int64: odd words are zero high-halves)
        int v0 = ei[2 * gt + 1];
        int is64 = __any_sync(0xffffffffu, v0 != 0) ? 0 : 1;
        // P1: in-degree count
        if (is64) { for (int e = gt; e < E; e += NT_B) atomicAdd(&g_deg[ei[2 * E + 2 * e]], 1); }
        else      { for (int e = gt; e < E; e += NT_B) atomicAdd(&g_deg[ei[E + e]], 1); }
        gbar_build();
        // P2: per-block region scan + dinv
        int chunk = (n + NBLK - 1) / NBLK;
        int r0 = b * chunk, r1 = min(r0 + chunk, n);
        if (tid == 0) s_carry = 0;
        bar_named(4, BW);
        for (int t0 = r0; t0 < r1; t0 += BW) {
            int i = t0 + tid;
            int deg = (i < r1) ? __ldcg(&g_deg[i]) : 0;
            int v = deg;
#pragma unroll
            for (int o = 1; o < 32; o <<= 1) {
                int t = __shfl_up_sync(0xffffffffu, v, o);
                if (lane >= o) v += t;
            }
            if (lane == 31) wsum[wid] = v;
            bar_named(4, BW);
            if (wid == 0 && lane < 8) {
                int s = wsum[lane];
#pragma unroll
                for (int o = 1; o < 8; o <<= 1) {
                    int t = __shfl_up_sync(0xffu, s, o);
                    if (lane >= o) s += t;
                }
                wsum[lane] = s;
            }
            bar_named(4, BW);
            int excl = s_carry + (wid ? wsum[wid - 1] : 0) + v - deg;
            if (i < r1) {
                g_off[i] = excl;
                g_dinv[i] = rsqrtf((float)deg + 1.0f);
            }
            bar_named(4, BW);
            if (tid == 0) s_carry += wsum[7];
            bar_named(4, BW);
        }
        if (tid == 0) g_bsum[b] = s_carry;
        gbar_build();
        // P3: block 0 scans region totals (148 values, 256 threads)
        if (b == 0) {
            int v = (tid < NBLK) ? __ldcg(&g_bsum[tid]) : 0;
            int xq = v;
#pragma unroll
            for (int o = 1; o < 32; o <<= 1) {
                int t = __shfl_up_sync(0xffffffffu, xq, o);
                if (lane >= o) xq += t;
            }
            if (lane == 31) wsum[wid] = xq;
            bar_named(4, BW);
            if (wid == 0 && lane < 8) {
                int s = wsum[lane];
#pragma unroll
                for (int o = 1; o < 8; o <<= 1) {
                    int t = __shfl_up_sync(0xffu, s, o);
                    if (lane >= o) s += t;
                }
                wsum[lane] = s;
            }
            bar_named(4, BW);
            if (tid < NBLK) g_bsum[tid] = (wid ? wsum[wid - 1] : 0) + xq - v;
        }
        gbar_build();
        // P4: add region base
        {
            int base = __ldcg(&g_bsum[b]);
            for (int i = r0 + tid; i < r1; i += BW) {
                int o = g_off[i] + base;
                g_off[i] = o;
                g_cur[i] = o;
            }
            if (gt == 0) g_off[n] = E;
        }
        gbar_build();
        // P5: place (src only)
        if (is64) {
            for (int e = gt; e < E; e += NT_B) {
                int s = ei[2 * e], d = ei[2 * E + 2 * e];
                g_csr[atomicAdd(&g_cur[d], 1)] = s;
            }
        } else {
            for (int e = gt; e < E; e += NT_B) {
                int s = ei[e], d = ei[E + e];
                g_csr[atomicAdd(&g_cur[d], 1)] = s;
            }
        }
    } else {
        // ---------- GEMM1: 3 groups x 256 threads, 64-row tiles, 4 rows/thread ----------
        int g = (tid >> 8) - 1;                   // 0..2
        int tg = tid & 255;
        int barid = 1 + g;
        float* ws = (float*)smem_dyn + g * (32 * 128);
        float* xs = (float*)(smem_dyn + WS_BYTES) + g * (32 * 68);
        int tr = tg >> 4;                         // 0..15 (4 rows each)
        int tc = tg & 15;                         // 0..15 (8 cols each)
        for (int t = b * NGRP + g; t * 64 < n; t += NBLK * NGRP) {
            int row0 = t * 64;
            ull acc[4][4];
#pragma unroll
            for (int r = 0; r < 4; ++r)
#pragma unroll
                for (int j = 0; j < 4; ++j) acc[r][j] = 0ull;
            for (int kc = 0; kc < 4; ++kc) {
                bar_named(barid, 256);
                for (int i = tg * 4; i < 32 * 128; i += 256 * 4)
                    *(float4*)(ws + i) = *(const float4*)(W1 + kc * 32 * 128 + i);
                for (int i = tg; i < 64 * 32; i += 256) {
                    int r = i >> 5, k = i & 31;
                    int gr = row0 + r;
                    xs[k * 68 + r] = (gr < n) ? x[(size_t)gr * 128 + kc * 32 + k] : 0.0f;
                }
                bar_named(barid, 256);
#pragma unroll 4
                for (int k = 0; k < 32; ++k) {
                    float4 xa = *(const float4*)&xs[k * 68 + tr * 4];
                    float4 wa = *(const float4*)&ws[k * 128 + tc * 8];
                    float4 wb = *(const float4*)&ws[k * 128 + tc * 8 + 4];
                    ull xd[4] = { pk2(xa.x, xa.x), pk2(xa.y, xa.y),
                                  pk2(xa.z, xa.z), pk2(xa.w, xa.w) };
                    {
                        ull wp = pk2(wa.x, wa.y);
#pragma unroll
                        for (int r = 0; r < 4; ++r) acc[r][0] = ffma2(xd[r], wp, acc[r][0]);
                    }
                    {
                        ull wp = pk2(wa.z, wa.w);
#pragma unroll
                        for (int r = 0; r < 4; ++r) acc[r][1] = ffma2(xd[r], wp, acc[r][1]);
                    }
                    {
                        ull wp = pk2(wb.x, wb.y);
#pragma unroll
                        for (int r = 0; r < 4; ++r) acc[r][2] = ffma2(xd[r], wp, acc[r][2]);
                    }
                    {
                        ull wp = pk2(wb.z, wb.w);
#pragma unroll
                        for (int r = 0; r < 4; ++r) acc[r][3] = ffma2(xd[r], wp, acc[r][3]);
                    }
                }
            }
#pragma unroll
            for (int r = 0; r < 4; ++r) {
                int gr = row0 + tr * 4 + r;
                if (gr >= n) continue;
                float2 p0 = up2(acc[r][0]), p1 = up2(acc[r][1]);
                float2 p2 = up2(acc[r][2]), p3 = up2(acc[r][3]);
                __half2 h[4] = { __float22half2_rn(p0), __float22half2_rn(p1),
                                 __float22half2_rn(p2), __float22half2_rn(p3) };
                *(uint4*)(g_h1 + (size_t)gr * 128 + tc * 8) = *(const uint4*)h;
            }
        }
    }

    gbar_full();

    // ================= PHASE 2: gather L1 + relu + fused GEMM2 =================
    float* w2s = (float*)smem_dyn;                        // [128][16]
    float* rowsb = (float*)(smem_dyn + 8192);             // [32][2][132]
    for (int i = tid; i < 2048; i += NTHR) w2s[i] = W2[i];
    __syncthreads();

    int warp = tid >> 5;
    int half = lane >> 4, hl = lane & 15;
    int c = hl << 3;
    int npair = (n + 1) >> 1;

    for (int pair = b * 32 + warp; pair < npair; pair += NBLK * 32) {
        int node = pair * 2 + half;
        float di = 0.0f;
        if (node < n) {
            di = g_dinv[node];
            ull acc[4] = {0ull, 0ull, 0ull, 0ull};
            {
                uint4 u = *(const uint4*)(g_h1 + (size_t)node * 128 + c);
                fma8p(acc, u, di);
            }
            int e = g_off[node], e1 = g_off[node + 1];
            for (; e + 4 <= e1; e += 4) {
                int s0 = g_csr[e],     s1 = g_csr[e + 1];
                int s2 = g_csr[e + 2], s3 = g_csr[e + 3];
                float w0 = g_dinv[s0], w1 = g_dinv[s1];
                float w2 = g_dinv[s2], w3 = g_dinv[s3];
                uint4 u0 = *(const uint4*)(g_h1 + (size_t)s0 * 128 + c);
                uint4 u1 = *(const uint4*)(g_h1 + (size_t)s1 * 128 + c);
                uint4 u2 = *(const uint4*)(g_h1 + (size_t)s2 * 128 + c);
                uint4 u3 = *(const uint4*)(g_h1 + (size_t)s3 * 128 + c);
                fma8p(acc, u0, w0);
                fma8p(acc, u1, w1);
                fma8p(acc, u2, w2);
                fma8p(acc, u3, w3);
            }
            for (; e < e1; ++e) {
                int s = g_csr[e];
                uint4 u = *(const uint4*)(g_h1 + (size_t)s * 128 + c);
                fma8p(acc, u, g_dinv[s]);
            }
            float4 ba = *(const float4*)(b1 + c);
            float4 bb = *(const float4*)(b1 + c + 4);
            float2 f0 = up2(acc[0]), f1 = up2(acc[1]);
            float2 f2 = up2(acc[2]), f3 = up2(acc[3]);
            float* rw = rowsb + (warp * 2 + half) * 132 + c;
            rw[0] = fmaxf(f0.x * di + ba.x, 0.0f);
            rw[1] = fmaxf(f0.y * di + ba.y, 0.0f);
            rw[2] = fmaxf(f1.x * di + ba.z, 0.0f);
            rw[3] = fmaxf(f1.y * di + ba.w, 0.0f);
            rw[4] = fmaxf(f2.x * di + bb.x, 0.0f);
            rw[5] = fmaxf(f2.y * di + bb.y, 0.0f);
            rw[6] = fmaxf(f3.x * di + bb.z, 0.0f);
            rw[7] = fmaxf(f3.y * di + bb.w, 0.0f);
        }
        __syncwarp();
        if (node < n) {
            const float* rr = rowsb + (warp * 2 + half) * 132;
            float s = 0.0f;
#pragma unroll 8
            for (int k = 0; k < 128; k += 4) {
                float4 r = *(const float4*)(rr + k);
                s += r.x * w2s[(k + 0) * 16 + hl];
                s += r.y * w2s[(k + 1) * 16 + hl];
                s += r.z * w2s[(k + 2) * 16 + hl];
                s += r.w * w2s[(k + 3) * 16 + hl];
            }
            g_h2[(size_t)node * 16 + hl] = s * di;     // pre-scaled for weight-free L2
        }
        __syncwarp();
    }

    gbar_full();

    // ================= PHASE 3: L2 (weight-free sum) + b2 + log_softmax; zero g_deg =================
    for (int i = b * NTHR + tid; i < n; i += NT_A) g_deg[i] = 0;   // for next replay
    for (int idx = b * NTHR + tid; idx < n * 4; idx += NT_A) {
        int node = idx >> 2;
        int q = (idx & 3) << 2;
        float di = g_dinv[node];
        float4 acc = *(const float4*)(g_h2 + (size_t)node * 16 + q);
        int e = g_off[node], e1 = g_off[node + 1];
        for (; e + 4 <= e1; e += 4) {
            int s0 = g_csr[e],     s1 = g_csr[e + 1];
            int s2 = g_csr[e + 2], s3 = g_csr[e + 3];
            float4 v0 = *(const float4*)(g_h2 + (size_t)s0 * 16 + q);
            float4 v1 = *(const float4*)(g_h2 + (size_t)s1 * 16 + q);
            float4 v2 = *(const float4*)(g_h2 + (size_t)s2 * 16 + q);
            float4 v3 = *(const float4*)(g_h2 + (size_t)s3 * 16 + q);
            acc.x += v0.x + v1.x + v2.x + v3.x;
            acc.y += v0.y + v1.y + v2.y + v3.y;
            acc.z += v0.z + v1.z + v2.z + v3.z;
            acc.w += v0.w + v1.w + v2.w + v3.w;
        }
        for (; e < e1; ++e) {
            int s = g_csr[e];
            float4 v = *(const float4*)(g_h2 + (size_t)s * 16 + q);
            acc.x += v.x; acc.y += v.y; acc.z += v.z; acc.w += v.w;
        }
        float4 bb = *(const float4*)(b2 + q);
        float4 v = make_float4(acc.x * di + bb.x, acc.y * di + bb.y,
                               acc.z * di + bb.z, acc.w * di + bb.w);
        float m = fmaxf(fmaxf(v.x, v.y), fmaxf(v.z, v.w));
        m = fmaxf(m, __shfl_xor_sync(0xffffffffu, m, 1, 4));
        m = fmaxf(m, __shfl_xor_sync(0xffffffffu, m, 2, 4));
        float s4 = expf(v.x - m) + expf(v.y - m) + expf(v.z - m) + expf(v.w - m);
        s4 += __shfl_xor_sync(0xffffffffu, s4, 1, 4);
        s4 += __shfl_xor_sync(0xffffffffu, s4, 2, 4);
        float L = m + logf(s4);
        *(float4*)(out + (size_t)node * 16 + q) =
            make_float4(v.x - L, v.y - L, v.z - L, v.w - L);
    }
}

// ---------------- launch: ONE kernel ----------------
extern "C" void kernel_launch(void* const* d_in, const int* in_sizes, int n_in,
                              void* d_out, int out_size) {
    const float* x  = (const float*)d_in[0];
    const int*   ei = (const int*)d_in[1];
    const float* W1 = (const float*)d_in[2];
    const float* b1 = (const float*)d_in[3];
    const float* W2 = (const float*)d_in[4];
    const float* b2 = (const float*)d_in[5];
    float* out = (float*)d_out;

    int n = in_sizes[0] / 128;
    int E = in_sizes[1] / 2;

    static bool inited = false;
    if (!inited) {
        cudaFuncSetAttribute(k_all, cudaFuncAttributeMaxDynamicSharedMemorySize, SMEM_BYTES);
        inited = true;
    }
    k_all<<<NBLK, NTHR, SMEM_BYTES>>>(x, ei, W1, b1, W2, b2, out, n, E);
}

// round 17
// speedup vs baseline: 1.2373x; 1.2373x over previous
#include <cuda_runtime.h>
#include <cuda_fp16.h>
#include <math.h>

#define NMAX 50000
#define EMAX 800000
#define NB1 148                  // build blocks (1/SM, co-resident)
#define BT1 1024
#define NT1 (NB1 * BT1)
#define NB2 592                  // gather blocks (4/SM via launch_bounds)

typedef unsigned long long ull;

// ---------------- scratch (static device memory) ----------------
__device__ float  g_dinv[NMAX];
__device__ int    g_deg[NMAX];            // zeroed by k_gather (prev replay / static init)
__device__ int    g_off[NMAX + 1];
__device__ int    g_cur[NMAX];
__device__ int    g_bsum[NB1 + 8];
__device__ int    g_csr[EMAX];            // src only (weights factor out)
__device__ __half g_h1[(size_t)NMAX * 128];  // x @ W1 (fp16)
__device__ float  g_h2[(size_t)NMAX * 16];   // (relu(agg1+b1) @ W2) * dinv

// ---------------- software grid barrier ----------------
__device__ unsigned g_cnt[2] = {0, 0};
__device__ volatile unsigned g_gen[2] = {0, 0};

__device__ __forceinline__ void gbar(int which, unsigned nb) {
    __syncthreads();
    if (threadIdx.x == 0) {
        __threadfence();
        unsigned g = g_gen[which];
        if (atomicAdd(&g_cnt[which], 1u) == nb - 1u) {
            g_cnt[which] = 0u;
            __threadfence();
            g_gen[which] = g + 1u;
        } else {
            while (g_gen[which] == g) __nanosleep(64);
        }
    }
    __syncthreads();
}

// ---------------- f32x2 packed math helpers ----------------
__device__ __forceinline__ ull pk2(float a, float b) {
    ull r; asm("mov.b64 %0, {%1, %2};" : "=l"(r) : "f"(a), "f"(b)); return r;
}
__device__ __forceinline__ float2 up2(ull v) {
    float2 r; asm("mov.b64 {%0, %1}, %2;" : "=f"(r.x), "=f"(r.y) : "l"(v)); return r;
}
__device__ __forceinline__ ull ffma2(ull a, ull b, ull c) {
    ull d; asm("fma.rn.f32x2 %0, %1, %2, %3;" : "=l"(d) : "l"(a), "l"(b), "l"(c)); return d;
}
__device__ __forceinline__ void fma8p(ull* acc, uint4 u, float w) {
    ull ww = pk2(w, w);
    __half2* h = (__half2*)&u;
#pragma unroll
    for (int j = 0; j < 4; ++j) {
        float2 f = __half22float2(h[j]);
        acc[j] = ffma2(pk2(f.x, f.y), ww, acc[j]);
    }
}

// ==================== fused CSR build (R14 proven) ====================
__global__ __launch_bounds__(BT1) void k_build(const int* __restrict__ ei, int n, int E) {
    __shared__ int wsum[32];
    __shared__ int s_carry;
    int tid = threadIdx.x, lane = tid & 31, wid = tid >> 5;
    int b = blockIdx.x;
    int gtid = b * BT1 + tid;

    int is64;
    {
        int v = ei[2 * gtid + 1];
        is64 = __syncthreads_or(v != 0) ? 0 : 1;
    }
    if (is64) {
        for (int e = gtid; e < E; e += NT1) atomicAdd(&g_deg[ei[2 * E + 2 * e]], 1);
    } else {
        for (int e = gtid; e < E; e += NT1) atomicAdd(&g_deg[ei[E + e]], 1);
    }
    gbar(0, NB1);

    int chunk = (n + NB1 - 1) / NB1;
    int r0 = b * chunk;
    int r1 = min(r0 + chunk, n);
    if (tid == 0) s_carry = 0;
    __syncthreads();
    for (int t0 = r0; t0 < r1; t0 += BT1) {
        int i = t0 + tid;
        int deg = (i < r1) ? __ldcg(&g_deg[i]) : 0;
        int v = deg;
#pragma unroll
        for (int o = 1; o < 32; o <<= 1) {
            int t = __shfl_up_sync(0xffffffffu, v, o);
            if (lane >= o) v += t;
        }
        if (lane == 31) wsum[wid] = v;
        __syncthreads();
        if (wid == 0) {
            int s = wsum[lane];
#pragma unroll
            for (int o = 1; o < 32; o <<= 1) {
                int t = __shfl_up_sync(0xffffffffu, s, o);
                if (lane >= o) s += t;
            }
            wsum[lane] = s;
        }
        __syncthreads();
        int excl = s_carry + (wid ? wsum[wid - 1] : 0) + v - deg;
        if (i < r1) {
            g_off[i] = excl;
            g_dinv[i] = rsqrtf((float)deg + 1.0f);
        }
        __syncthreads();
        if (tid == 0) s_carry += wsum[31];
        __syncthreads();
    }
    if (tid == 0) g_bsum[b] = s_carry;
    gbar(0, NB1);

    if (b == 0) {
        int v = (tid < NB1) ? __ldcg(&g_bsum[tid]) : 0;
        int x = v;
#pragma unroll
        for (int o = 1; o < 32; o <<= 1) {
            int t = __shfl_up_sync(0xffffffffu, x, o);
            if (lane >= o) x += t;
        }
        if (lane == 31) wsum[wid] = x;
        __syncthreads();
        if (wid == 0) {
            int s = wsum[lane];
#pragma unroll
            for (int o = 1; o < 32; o <<= 1) {
                int t = __shfl_up_sync(0xffffffffu, s, o);
                if (lane >= o) s += t;
            }
            wsum[lane] = s;
        }
        __syncthreads();
        if (tid < NB1) g_bsum[tid] = (wid ? wsum[wid - 1] : 0) + x - v;
    }
    gbar(0, NB1);

    {
        int base = __ldcg(&g_bsum[b]);
        for (int i = r0 + tid; i < r1; i += BT1) {
            int o = g_off[i] + base;
            g_off[i] = o;
            g_cur[i] = o;
        }
        if (gtid == 0) g_off[n] = E;
    }
    gbar(0, NB1);

    if (is64) {
        for (int e = gtid; e < E; e += NT1) {
            int s = ei[2 * e], d = ei[2 * E + 2 * e];
            g_csr[atomicAdd(&g_cur[d], 1)] = s;
        }
    } else {
        for (int e = gtid; e < E; e += NT1) {
            int s = ei[e], d = ei[E + e];
            g_csr[atomicAdd(&g_cur[d], 1)] = s;
        }
    }
}

// ==================== GEMM1 via HMMA (mma.sync m16n8k16): h1 = x @ W1 -> fp16 ====================
// Block: 128 threads (4 warps). Tile: 64 rows x 128 cols. Warp: 16 rows x 128 cols.
// A: [64][136] fp16 (row-major, padded). B = W1^T: [n][k] = [128][136] fp16.
// K loop: 8 steps of 16. Per warp per k-step: 4 a-regs, 16 n8-tiles (2 b-regs + 1 mma each).
#define GA_PAD 136
__global__ __launch_bounds__(128) void k_gemm1_mma(const float* __restrict__ x,
                                                   const float* __restrict__ W,
                                                   int n) {
    extern __shared__ __half smh[];
    __half* As = smh;                       // 64*136
    __half* Bs = smh + 64 * GA_PAD;         // 128*136
    int tid = threadIdx.x, warp = tid >> 5, lane = tid & 31;
    int row0 = blockIdx.x * 64;

    // fill Bs[n][k] = W1[k][n]  (coalesced global reads)
    for (int i = tid; i < 128 * 128; i += 128) {
        int k = i >> 7, nn = i & 127;
        Bs[nn * GA_PAD + k] = __float2half(W[k * 128 + nn]);
    }
    // fill As rows (coalesced float4 reads, fp16 convert)
    for (int i = tid * 4; i < 64 * 128; i += 128 * 4) {
        int r = i >> 7, k = i & 127;
        int gr = row0 + r;
        __half2 h2[2];
        if (gr < n) {
            float4 v = *(const float4*)(x + (size_t)gr * 128 + k);
            h2[0] = __floats2half2_rn(v.x, v.y);
            h2[1] = __floats2half2_rn(v.z, v.w);
        } else {
            h2[0] = __floats2half2_rn(0.0f, 0.0f);
            h2[1] = h2[0];
        }
        *(uint2*)(As + r * GA_PAD + k) = *(const uint2*)h2;
    }
    __syncthreads();

    float acc[16][4];
#pragma unroll
    for (int t = 0; t < 16; ++t)
#pragma unroll
        for (int j = 0; j < 4; ++j) acc[t][j] = 0.0f;

    int r = lane >> 2;              // 0..7
    int c0 = (lane & 3) * 2;        // 0,2,4,6
    const __half* Ab = As + (warp * 16) * GA_PAD;
    int bn = lane >> 2;             // n within tile
    int bk = (lane & 3) * 2;        // k within tile

#pragma unroll
    for (int k8 = 0; k8 < 8; ++k8) {
        int kb = k8 * 16;
        unsigned a0 = *(const unsigned*)(Ab + r * GA_PAD + kb + c0);
        unsigned a1 = *(const unsigned*)(Ab + (r + 8) * GA_PAD + kb + c0);
        unsigned a2 = *(const unsigned*)(Ab + r * GA_PAD + kb + c0 + 8);
        unsigned a3 = *(const unsigned*)(Ab + (r + 8) * GA_PAD + kb + c0 + 8);
#pragma unroll
        for (int t = 0; t < 16; ++t) {
            const __half* Bp = Bs + (t * 8 + bn) * GA_PAD + kb + bk;
            unsigned b0 = *(const unsigned*)Bp;
            unsigned b1 = *(const unsigned*)(Bp + 8);
            asm volatile(
                "mma.sync.aligned.m16n8k16.row.col.f32.f16.f16.f32 "
                "{%0,%1,%2,%3}, {%4,%5,%6,%7}, {%8,%9}, {%0,%1,%2,%3};"
                : "+f"(acc[t][0]), "+f"(acc[t][1]), "+f"(acc[t][2]), "+f"(acc[t][3])
                : "r"(a0), "r"(a1), "r"(a2), "r"(a3), "r"(b0), "r"(b1));
        }
    }

    // store: D[r][cc],D[r][cc+1] and D[r+8][..] per tile; half2 per pair
    int gr0 = row0 + warp * 16 + r;
    int gr1 = gr0 + 8;
#pragma unroll
    for (int t = 0; t < 16; ++t) {
        int col = t * 8 + c0;
        if (gr0 < n) {
            __half2 h = __floats2half2_rn(acc[t][0], acc[t][1]);
            *(unsigned*)(g_h1 + (size_t)gr0 * 128 + col) = *(const unsigned*)&h;
        }
        if (gr1 < n) {
            __half2 h = __floats2half2_rn(acc[t][2], acc[t][3]);
            *(unsigned*)(g_h1 + (size_t)gr1 * 128 + col) = *(const unsigned*)&h;
        }
    }
}

// ==================== fused gathers (R14 proven) ====================
__global__ __launch_bounds__(256, 4) void k_gather(float* __restrict__ out,
                                                   const float* __restrict__ b1,
                                                   const float* __restrict__ W2,
                                                   const float* __restrict__ b2,
                                                   int n) {
    __shared__ float w2s[128 * 16];
    __shared__ float rows[8][2][132];
    int tid = threadIdx.x;
    for (int i = tid; i < 2048; i += 256) w2s[i] = W2[i];
    for (int i = blockIdx.x * 256 + tid; i < n; i += NB2 * 256) g_deg[i] = 0;
    __syncthreads();

    int warp = tid >> 5, lane = tid & 31;
    int half = lane >> 4, hl = lane & 15;
    int c = hl << 3;
    int npair = (n + 1) >> 1;

    for (int pair = blockIdx.x * 8 + warp; pair < npair; pair += NB2 * 8) {
        int node = pair * 2 + half;
        float di = 0.0f;
        if (node < n) {
            di = g_dinv[node];
            ull acc[4] = {0ull, 0ull, 0ull, 0ull};
            {
                uint4 u = *(const uint4*)(g_h1 + (size_t)node * 128 + c);
                fma8p(acc, u, di);
            }
            int e = g_off[node], e1 = g_off[node + 1];
            for (; e + 4 <= e1; e += 4) {
                int s0 = g_csr[e],     s1 = g_csr[e + 1];
                int s2 = g_csr[e + 2], s3 = g_csr[e + 3];
                float w0 = g_dinv[s0], w1 = g_dinv[s1];
                float w2 = g_dinv[s2], w3 = g_dinv[s3];
                uint4 u0 = *(const uint4*)(g_h1 + (size_t)s0 * 128 + c);
                uint4 u1 = *(const uint4*)(g_h1 + (size_t)s1 * 128 + c);
                uint4 u2 = *(const uint4*)(g_h1 + (size_t)s2 * 128 + c);
                uint4 u3 = *(const uint4*)(g_h1 + (size_t)s3 * 128 + c);
                fma8p(acc, u0, w0);
                fma8p(acc, u1, w1);
                fma8p(acc, u2, w2);
                fma8p(acc, u3, w3);
            }
            for (; e < e1; ++e) {
                int s = g_csr[e];
                uint4 u = *(const uint4*)(g_h1 + (size_t)s * 128 + c);
                fma8p(acc, u, g_dinv[s]);
            }
            float4 ba = *(const float4*)(b1 + c);
            float4 bb = *(const float4*)(b1 + c + 4);
            float2 f0 = up2(acc[0]), f1 = up2(acc[1]);
            float2 f2 = up2(acc[2]), f3 = up2(acc[3]);
            float* rw = &rows[warp][half][c];
            rw[0] = fmaxf(f0.x * di + ba.x, 0.0f);
            rw[1] = fmaxf(f0.y * di + ba.y, 0.0f);
            rw[2] = fmaxf(f1.x * di + ba.z, 0.0f);
            rw[3] = fmaxf(f1.y * di + ba.w, 0.0f);
            rw[4] = fmaxf(f2.x * di + bb.x, 0.0f);
            rw[5] = fmaxf(f2.y * di + bb.y, 0.0f);
            rw[6] = fmaxf(f3.x * di + bb.z, 0.0f);
            rw[7] = fmaxf(f3.y * di + bb.w, 0.0f);
        }
        __syncwarp();
        if (node < n) {
            const float* rr = &rows[warp][half][0];
            float s = 0.0f;
#pragma unroll 8
            for (int k = 0; k < 128; k += 4) {
                float4 r = *(const float4*)(rr + k);
                s += r.x * w2s[(k + 0) * 16 + hl];
                s += r.y * w2s[(k + 1) * 16 + hl];
                s += r.z * w2s[(k + 2) * 16 + hl];
                s += r.w * w2s[(k + 3) * 16 + hl];
            }
            g_h2[(size_t)node * 16 + hl] = s * di;
        }
        __syncwarp();
    }

    gbar(1, NB2);

    for (int idx = blockIdx.x * 256 + tid; idx < n * 4; idx += NB2 * 256) {
        int node = idx >> 2;
        int q = (idx & 3) << 2;
        float di = g_dinv[node];
        float4 acc = *(const float4*)(g_h2 + (size_t)node * 16 + q);
        int e = g_off[node], e1 = g_off[node + 1];
        for (; e + 4 <= e1; e += 4) {
            int s0 = g_csr[e],     s1 = g_csr[e + 1];
            int s2 = g_csr[e + 2], s3 = g_csr[e + 3];
            float4 v0 = *(const float4*)(g_h2 + (size_t)s0 * 16 + q);
            float4 v1 = *(const float4*)(g_h2 + (size_t)s1 * 16 + q);
            float4 v2 = *(const float4*)(g_h2 + (size_t)s2 * 16 + q);
            float4 v3 = *(const float4*)(g_h2 + (size_t)s3 * 16 + q);
            acc.x += v0.x + v1.x + v2.x + v3.x;
            acc.y += v0.y + v1.y + v2.y + v3.y;
            acc.z += v0.z + v1.z + v2.z + v3.z;
            acc.w += v0.w + v1.w + v2.w + v3.w;
        }
        for (; e < e1; ++e) {
            int s = g_csr[e];
            float4 v = *(const float4*)(g_h2 + (size_t)s * 16 + q);
            acc.x += v.x; acc.y += v.y; acc.z += v.z; acc.w += v.w;
        }
        float4 b = *(const float4*)(b2 + q);
        float4 v = make_float4(acc.x * di + b.x, acc.y * di + b.y,
                               acc.z * di + b.z, acc.w * di + b.w);
        float m = fmaxf(fmaxf(v.x, v.y), fmaxf(v.z, v.w));
        m = fmaxf(m, __shfl_xor_sync(0xffffffffu, m, 1, 4));
        m = fmaxf(m, __shfl_xor_sync(0xffffffffu, m, 2, 4));
        float s4 = expf(v.x - m) + expf(v.y - m) + expf(v.z - m) + expf(v.w - m);
        s4 += __shfl_xor_sync(0xffffffffu, s4, 1, 4);
        s4 += __shfl_xor_sync(0xffffffffu, s4, 2, 4);
        float L = m + logf(s4);
        *(float4*)(out + (size_t)node * 16 + q) =
            make_float4(v.x - L, v.y - L, v.z - L, v.w - L);
    }
}

// ---------------- launch: fork/join, build || hmma-gemm1, then fused gather ----------------
extern "C" void kernel_launch(void* const* d_in, const int* in_sizes, int n_in,
                              void* d_out, int out_size) {
    const float* x  = (const float*)d_in[0];
    const int*   ei = (const int*)d_in[1];
    const float* W1 = (const float*)d_in[2];
    const float* b1 = (const float*)d_in[3];
    const float* W2 = (const float*)d_in[4];
    const float* b2 = (const float*)d_in[5];
    float* out = (float*)d_out;

    int n = in_sizes[0] / 128;
    int E = in_sizes[1] / 2;
    int ntile = (n + 63) / 64;
    int smem_g = (64 * GA_PAD + 128 * GA_PAD) * 2;   // 52224 bytes

    static cudaStream_t s1 = nullptr, s2 = nullptr;
    static cudaEvent_t ev0 = nullptr, ev1 = nullptr, ev2 = nullptr;
    if (!s1) {
        cudaStreamCreateWithFlags(&s1, cudaStreamNonBlocking);
        cudaStreamCreateWithFlags(&s2, cudaStreamNonBlocking);
        cudaEventCreateWithFlags(&ev0, cudaEventDisableTiming);
        cudaEventCreateWithFlags(&ev1, cudaEventDisableTiming);
        cudaEventCreateWithFlags(&ev2, cudaEventDisableTiming);
        cudaFuncSetAttribute(k_gemm1_mma, cudaFuncAttributeMaxDynamicSharedMemorySize, 65536);
    }

    cudaEventRecord(ev0, 0);
    cudaStreamWaitEvent(s1, ev0, 0);
    cudaStreamWaitEvent(s2, ev0, 0);

    k_build<<<NB1, BT1, 0, s1>>>(ei, n, E);
    cudaEventRecord(ev1, s1);

    k_gemm1_mma<<<ntile, 128, smem_g, s2>>>(x, W1, n);
    cudaEventRecord(ev2, s2);

    cudaStreamWaitEvent(0, ev1, 0);
    cudaStreamWaitEvent(0, ev2, 0);

    k_gather<<<NB2, 256>>>(out, b1, W2, b2, n);
}